// round 1
// baseline (speedup 1.0000x reference)
#include <cuda_runtime.h>
#include <math.h>

#define BATCH 8
#define CHN   16
#define NN    64
#define KT    12
#define KXY   24
#define N3INV (1.0f/262144.0f)

// ---------------- scratch (static device memory; no allocations) ----------------
__device__ float2 g_A [BATCH*CHN*NN*NN*KT];     // 6,291,456 c  (A after T-DFT; reused as F after inv-Y)
__device__ float2 g_Bf[BATCH*CHN*NN*KXY*KT];    // 2,359,296 c  (Bf after Y-DFT; reused as E after inv-X)
__device__ float2 g_D [BATCH*CHN*KXY*KXY*KT];   //   884,736 c  (spectral-multiplied modes)
__device__ float2 g_W [KXY*KXY*KT*CHN*CHN];     // 1,769,472 c  (repacked weights, mode-major)
__device__ float2 g_twT [KT*NN];                // forward T twiddle  (cos, sin)
__device__ float2 g_twXY[KXY*NN];               // X/Y twiddle for the 24 kept freqs
__device__ float2 g_twTi[KT*NN];                // inverse-T table with 1/N^3 folded in

// ---------------- init: twiddle tables (rebuilt every launch) ----------------
__global__ void k_init() {
    int idx = blockIdx.x * blockDim.x + threadIdx.x;
    if (idx < KT*NN) {
        int k = idx / NN, t = idx % NN;
        int m = (k * t) & 63;
        float s, c;
        sincospif((float)m / 32.0f, &s, &c);
        g_twT[idx] = make_float2(c, s);
        if (k == 0) g_twTi[idx] = make_float2(N3INV, 0.0f);
        else        g_twTi[idx] = make_float2(2.0f*c*N3INV, -2.0f*s*N3INV);
    } else if (idx < KT*NN + KXY*NN) {
        int r = idx - KT*NN;
        int j = r / NN, t = r % NN;
        int f = (j < 12) ? j : j + 40;   // freqs 0..11, 52..63
        int m = (f * t) & 63;
        float s, c;
        sincospif((float)m / 32.0f, &s, &c);
        g_twXY[r] = make_float2(c, s);
    }
}

// ---------------- repack w1..w4 -> g_W[(kx*24+ky)*12+kz][i][o] ----------------
__global__ void k_repack(const float* __restrict__ w1, const float* __restrict__ w2,
                         const float* __restrict__ w3, const float* __restrict__ w4) {
    int idx = blockIdx.x * blockDim.x + threadIdx.x;
    if (idx >= KXY*KXY*KT*CHN*CHN) return;
    int o = idx & 15;
    int i = (idx >> 4) & 15;
    int r = idx >> 8;                   // (kxi*24+kyi)*12+kz
    int kz  = r % 12;  r /= 12;
    int kyi = r % 24;
    int kxi = r / 24;
    int jx = (kxi < 12) ? kxi : kxi - 12;
    int jy = (kyi < 12) ? kyi : kyi - 12;
    const float* w = (kxi < 12) ? ((kyi < 12) ? w1 : w3)
                                : ((kyi < 12) ? w2 : w4);
    // w[i][o][jx][jy][kz][2]
    int src = (i*16 + o)*1728 + (jx*12 + jy)*12 + kz;
    g_W[idx] = reinterpret_cast<const float2*>(w)[src];
}

// ---------------- K1: real DFT over T, 64 -> 12 bins ----------------
// block = 2 slabs of (b,c,x); 256 threads; thread = (slab, y, half of kz)
__global__ void __launch_bounds__(256) k_dft_t(const float* __restrict__ x) {
    __shared__ float  s[2*NN*65];
    __shared__ float2 stw[KT*NN];
    int slab0 = blockIdx.x * 2;
    for (int i = threadIdx.x; i < 2*4096; i += 256) {
        int sl = i >> 12, r = i & 4095;
        int yy = r >> 6, tt = r & 63;
        s[sl*(NN*65) + yy*65 + tt] = x[(size_t)(slab0 + sl)*4096 + r];
    }
    for (int i = threadIdx.x; i < KT*NN; i += 256) stw[i] = g_twT[i];
    __syncthreads();

    int sl   = threadIdx.x >> 7;
    int tloc = threadIdx.x & 127;
    int yy   = tloc & 63;
    int kb   = (tloc >> 6) * 6;           // kz base: 0 or 6
    const float* row = &s[sl*(NN*65) + yy*65];
    float ar[6], ai[6];
#pragma unroll
    for (int j = 0; j < 6; j++) { ar[j] = 0.f; ai[j] = 0.f; }
#pragma unroll 4
    for (int t = 0; t < 64; t++) {
        float v = row[t];
#pragma unroll
        for (int j = 0; j < 6; j++) {
            float2 w = stw[(kb + j)*64 + t];   // uniform across warp -> broadcast
            ar[j] += v * w.x;                  // e^{-i th}: re += v*c
            ai[j] -= v * w.y;                  //            im -= v*s
        }
    }
    float2* dst = g_A + (size_t)(slab0 + sl)*NN*KT + yy*KT + kb;
#pragma unroll
    for (int j = 0; j < 6; j++) dst[j] = make_float2(ar[j], ai[j]);
}

// ---------------- K2: complex DFT over Y, 64 -> 24 bins ----------------
// block = 2 slabs of (b,c,x); 288 threads; thread = (slab, ky, kz-pair)
__global__ void __launch_bounds__(288) k_dft_y() {
    __shared__ float2 sA[2*NN*KT];
    __shared__ float2 stw[KXY*NN];
    int slab0 = blockIdx.x * 2;
    for (int i = threadIdx.x; i < 2*768; i += 288) {
        int sl = i / 768, r = i % 768;
        sA[i] = g_A[(size_t)(slab0 + sl)*768 + r];
    }
    for (int i = threadIdx.x; i < 1536; i += 288) stw[i] = g_twXY[i];
    __syncthreads();

    int sl   = threadIdx.x / 144;
    int tloc = threadIdx.x % 144;
    int ky = tloc / 6;
    int k0 = (tloc % 6) * 2;
    const float2* a0 = &sA[sl*768];
    const float2* tw = &stw[ky*64];
    float2 acc0 = make_float2(0.f, 0.f), acc1 = make_float2(0.f, 0.f);
#pragma unroll 4
    for (int yy = 0; yy < 64; yy++) {
        float2 w = tw[yy];
        float2 a = a0[yy*12 + k0];
        float2 b = a0[yy*12 + k0 + 1];
        acc0.x += a.x*w.x + a.y*w.y;  acc0.y += a.y*w.x - a.x*w.y;   // * e^{-i th}
        acc1.x += b.x*w.x + b.y*w.y;  acc1.y += b.y*w.x - b.x*w.y;
    }
    float2* dst = g_Bf + (size_t)(slab0 + sl)*288 + ky*12 + k0;
    dst[0] = acc0; dst[1] = acc1;
}

// ---------------- K3: complex DFT over X (64 -> 24) fused with spectral 16x16 mix ----------------
// block = (b, ky, kz); 384 threads
__global__ void __launch_bounds__(384) k_dft_x_mul() {
    __shared__ float2 sIn[CHN*65];     // [c][x], padded
    __shared__ float2 sAcc[KXY*CHN];   // a-hat[kx][c]
    __shared__ float2 stw[KXY*NN];
    int blk = blockIdx.x;
    int b  = blk / 288;
    int r  = blk % 288;
    int ky = r / 12, kz = r % 12;

    for (int i = threadIdx.x; i < 1024; i += 384) {
        int c = i >> 6, xx = i & 63;
        sIn[c*65 + xx] = g_Bf[(((size_t)(b*16 + c)*64 + xx)*24 + ky)*12 + kz];
    }
    for (int i = threadIdx.x; i < 1536; i += 384) stw[i] = g_twXY[i];
    __syncthreads();

    {   // stage 1: X DFT -> sAcc[kx][c]
        int kx = threadIdx.x >> 4, c = threadIdx.x & 15;
        const float2* tw = &stw[kx*64];
        const float2* a  = &sIn[c*65];
        float2 acc = make_float2(0.f, 0.f);
#pragma unroll 4
        for (int xx = 0; xx < 64; xx++) {
            float2 w = tw[xx]; float2 v = a[xx];
            acc.x += v.x*w.x + v.y*w.y;
            acc.y += v.y*w.x - v.x*w.y;
        }
        sAcc[kx*16 + c] = acc;
    }
    __syncthreads();
    {   // stage 2: per-mode complex channel mix, write D[b][o][ky][kx][kz]
        int kx = threadIdx.x >> 4, o = threadIdx.x & 15;
        const float2* Wp = g_W + ((size_t)((kx*24 + ky)*12 + kz)) * 256;
        float2 acc = make_float2(0.f, 0.f);
#pragma unroll
        for (int i = 0; i < 16; i++) {
            float2 av = sAcc[kx*16 + i];
            float2 w  = Wp[i*16 + o];
            acc.x += av.x*w.x - av.y*w.y;
            acc.y += av.x*w.y + av.y*w.x;
        }
        g_D[(((size_t)(b*16 + o)*24 + ky)*24 + kx)*12 + kz] = acc;
    }
}

// ---------------- K5: inverse DFT over X (24 kept bins -> 64) ----------------
// block = (b*16+o, ky); 384 threads; thread = (x, kz-pair)
__global__ void __launch_bounds__(384) k_idft_x() {
    __shared__ float2 sD[KXY*KT];
    __shared__ float2 stw[KXY*NN];
    int blk = blockIdx.x;
    int bo = blk / 24, ky = blk % 24;
    for (int i = threadIdx.x; i < 288; i += 384) sD[i] = g_D[(size_t)blk*288 + i];
    for (int i = threadIdx.x; i < 1536; i += 384) stw[i] = g_twXY[i];
    __syncthreads();

    int xx = threadIdx.x / 6;
    int k0 = (threadIdx.x % 6) * 2;
    float2 acc0 = make_float2(0.f, 0.f), acc1 = make_float2(0.f, 0.f);
#pragma unroll
    for (int kx = 0; kx < 24; kx++) {
        float2 w = stw[kx*64 + xx];
        float2 a = sD[kx*12 + k0];
        float2 b = sD[kx*12 + k0 + 1];
        acc0.x += a.x*w.x - a.y*w.y;  acc0.y += a.x*w.y + a.y*w.x;   // * e^{+i th}
        acc1.x += b.x*w.x - b.y*w.y;  acc1.y += b.x*w.y + b.y*w.x;
    }
    float2* dst = g_Bf + (((size_t)bo*64 + xx)*24 + ky)*12 + k0;
    dst[0] = acc0; dst[1] = acc1;
}

// ---------------- K6: inverse DFT over Y (24 kept bins -> 64) ----------------
// block = (b*16+o, x); 384 threads; thread = (y, kz-pair)
__global__ void __launch_bounds__(384) k_idft_y() {
    __shared__ float2 sE[KXY*KT];
    __shared__ float2 stw[KXY*NN];
    int blk = blockIdx.x;   // bo*64 + xx
    for (int i = threadIdx.x; i < 288; i += 384) sE[i] = g_Bf[(size_t)blk*288 + i];
    for (int i = threadIdx.x; i < 1536; i += 384) stw[i] = g_twXY[i];
    __syncthreads();

    int yy = threadIdx.x / 6;
    int k0 = (threadIdx.x % 6) * 2;
    float2 acc0 = make_float2(0.f, 0.f), acc1 = make_float2(0.f, 0.f);
#pragma unroll
    for (int ky = 0; ky < 24; ky++) {
        float2 w = stw[ky*64 + yy];
        float2 a = sE[ky*12 + k0];
        float2 b = sE[ky*12 + k0 + 1];
        acc0.x += a.x*w.x - a.y*w.y;  acc0.y += a.x*w.y + a.y*w.x;
        acc1.x += b.x*w.x - b.y*w.y;  acc1.y += b.x*w.y + b.y*w.x;
    }
    float2* dst = g_A + (size_t)blk*768 + yy*12 + k0;
    dst[0] = acc0; dst[1] = acc1;
}

// ---------------- K7: inverse rfft over T + ReLU + 16x16 mix + bias ----------------
// block = (b, x, y-group-of-8); 256 threads; one warp per y line; lane owns t and t+32
__global__ void __launch_bounds__(256) k_ifft_t_mix(const float* __restrict__ lo_w,
                                                    const float* __restrict__ lo_b,
                                                    float* __restrict__ out) {
    __shared__ float2 sF[8*CHN*KT];    // [slab][c][k]
    __shared__ float2 sTi[KT*NN];
    __shared__ float  sW[256];
    __shared__ float  sB[16];
    int blk = blockIdx.x;              // (b*64+xx)*8 + ygrp
    int b   = blk >> 9;
    int rr  = blk & 511;
    int xx  = rr >> 3;
    int yy0 = (rr & 7) * 8;

    for (int i = threadIdx.x; i < 1536; i += 256) {
        int sl = i / 192, r2 = i % 192;
        int c = r2 / 12, k = r2 % 12;
        sF[i] = g_A[((((size_t)(b*16 + c)*64 + xx)*64) + yy0 + sl)*12 + k];
    }
    for (int i = threadIdx.x; i < 768; i += 256) sTi[i] = g_twTi[i];
    if (threadIdx.x < 256) sW[threadIdx.x] = lo_w[threadIdx.x];
    if (threadIdx.x < 16)  sB[threadIdx.x] = lo_b[threadIdx.x];
    __syncthreads();

    int w    = threadIdx.x >> 5;
    int lane = threadIdx.x & 31;
    int yy   = yy0 + w;
    const float2* F = &sF[w*192];

    float acc[CHN][2];
#pragma unroll
    for (int c = 0; c < 16; c++) { acc[c][0] = 0.f; acc[c][1] = 0.f; }
#pragma unroll
    for (int k = 0; k < 12; k++) {
        float2 a0 = sTi[k*64 + lane];
        float2 a1 = sTi[k*64 + lane + 32];
#pragma unroll
        for (int c = 0; c < 16; c++) {
            float2 f = F[c*12 + k];                 // warp-uniform -> broadcast
            acc[c][0] += f.x*a0.x + f.y*a0.y;       // Re*A + Im*B  (A,B have 1/N^3, 2x folded)
            acc[c][1] += f.x*a1.x + f.y*a1.y;
        }
    }
#pragma unroll
    for (int c = 0; c < 16; c++) {
        acc[c][0] = fmaxf(acc[c][0], 0.f);
        acc[c][1] = fmaxf(acc[c][1], 0.f);
    }
#pragma unroll
    for (int o = 0; o < 16; o++) {
        float r0 = sB[o], r1 = sB[o];
#pragma unroll
        for (int c = 0; c < 16; c++) {
            float wv = sW[o*16 + c];
            r0 += acc[c][0] * wv;
            r1 += acc[c][1] * wv;
        }
        float* dst = out + ((((size_t)(b*16 + o)*64 + xx)*64 + yy)*64);
        dst[lane]      = r0;
        dst[lane + 32] = r1;
    }
}

// ---------------- launch ----------------
extern "C" void kernel_launch(void* const* d_in, const int* in_sizes, int n_in,
                              void* d_out, int out_size) {
    const float* x    = (const float*)d_in[0];
    const float* w1   = (const float*)d_in[1];
    const float* w2   = (const float*)d_in[2];
    const float* w3   = (const float*)d_in[3];
    const float* w4   = (const float*)d_in[4];
    const float* lo_w = (const float*)d_in[5];
    const float* lo_b = (const float*)d_in[6];
    float* out = (float*)d_out;

    k_init<<<9, 256>>>();
    k_repack<<<6912, 256>>>(w1, w2, w3, w4);
    k_dft_t<<<4096, 256>>>(x);                       // [b,c,x] slabs: T 64 -> 12
    k_dft_y<<<4096, 288>>>();                        // Y 64 -> 24
    k_dft_x_mul<<<2304, 384>>>();                    // X 64 -> 24 + per-mode channel mix
    k_idft_x<<<3072, 384>>>();                       // X 24 -> 64
    k_idft_y<<<8192, 384>>>();                       // Y 24 -> 64
    k_ifft_t_mix<<<4096, 256>>>(lo_w, lo_b, out);    // T 12 -> 64 + relu + 1x1 conv
}